// round 13
// baseline (speedup 1.0000x reference)
#include <cuda_runtime.h>
#include <cuda_bf16.h>
#include <math.h>

#define B_  4
#define Nn  384
#define E_  768
#define H_  32
#define F_  3072
#define L_  12
#define S_  512
#define D_  24
#define T_  (B_*Nn)          // 1536 tokens
#define QKV 2304             // 3*E

// -------------------- scratch (static device allocations) --------------------
__device__ float g_x   [T_*E_];
__device__ float g_tmp [T_*E_];
__device__ float g_qkv [T_*QKV];
__device__ float g_bias[B_*H_*Nn*Nn];
__device__ float g_bqkv[L_*QKV];
// bf16 hi/lo activation buffers
__device__ __nv_bfloat16 g_xh[T_*E_],  g_xl[T_*E_];
__device__ __nv_bfloat16 g_ch[T_*E_],  g_cl[T_*E_];
__device__ __nv_bfloat16 g_hh[T_*F_],  g_hl[T_*F_];
// bf16 hi/lo transposed weights, [l][n][k]
__device__ __nv_bfloat16 g_wqkvh[(size_t)L_*QKV*E_], g_wqkvl[(size_t)L_*QKV*E_];
__device__ __nv_bfloat16 g_woh  [(size_t)L_*E_*E_],  g_wol  [(size_t)L_*E_*E_];
__device__ __nv_bfloat16 g_w1h  [(size_t)L_*F_*E_],  g_w1l  [(size_t)L_*F_*E_];
__device__ __nv_bfloat16 g_w2h  [(size_t)L_*E_*F_],  g_w2l  [(size_t)L_*E_*F_];

// ==================== helpers ====================
__device__ __forceinline__ float gelu_f(float x) {
    return 0.5f * x * (1.0f + tanhf(0.7978845608028654f * (x + 0.044715f * x * x * x)));
}
__device__ __forceinline__ unsigned smem_u32(const void* p) {
    return (unsigned)__cvta_generic_to_shared(p);
}
#define CP_ASYNC16(dst, src) \
    asm volatile("cp.async.cg.shared.global [%0], [%1], 16;\n" :: "r"(dst), "l"(src) : "memory")
#define CP_COMMIT() asm volatile("cp.async.commit_group;\n" ::: "memory")
#define CP_WAIT1()  asm volatile("cp.async.wait_group 1;\n" ::: "memory")

#define MMA_BF16(acc, a, b) \
    asm volatile("mma.sync.aligned.m16n8k16.row.col.f32.bf16.bf16.f32 " \
        "{%0,%1,%2,%3}, {%4,%5,%6,%7}, {%8,%9}, {%0,%1,%2,%3};" \
        : "+f"((acc)[0]), "+f"((acc)[1]), "+f"((acc)[2]), "+f"((acc)[3]) \
        : "r"((a)[0]), "r"((a)[1]), "r"((a)[2]), "r"((a)[3]), "r"((b)[0]), "r"((b)[1]))

#define LDMX4(r0, r1, r2, r3, addr) \
    asm volatile("ldmatrix.sync.aligned.m8n8.x4.shared.b16 {%0,%1,%2,%3}, [%4];" \
        : "=r"(r0), "=r"(r1), "=r"(r2), "=r"(r3) : "r"(addr))

__device__ __forceinline__ void split_bf(float v, __nv_bfloat16& h, __nv_bfloat16& l) {
    h = __float2bfloat16_rn(v);
    l = __float2bfloat16_rn(v - __bfloat162float(h));
}

// ==================== ALL weight transposes in ONE kernel ====================
// Pieces (1D grid decode):
//   [0, 27648)           : Wq/Wk/Wv/Wo ExE  (which=0..3, 24x24 tiles per layer)
//   [27648, 55296)       : W1  (src [E,F], dst [F,E]; 96x24 tiles per layer)
//   [55296, 82944)       : W2  (src [F,E], dst [E,F]; 24x96 tiles per layer)
#define TRALL_BLOCKS 82944
__global__ void __launch_bounds__(256)
trall_k(const float* __restrict__ Wq, const float* __restrict__ Wk,
        const float* __restrict__ Wv, const float* __restrict__ Wo,
        const float* __restrict__ W1, const float* __restrict__ W2,
        __nv_bfloat16* __restrict__ qh, __nv_bfloat16* __restrict__ ql,
        __nv_bfloat16* __restrict__ ohp, __nv_bfloat16* __restrict__ olp,
        __nv_bfloat16* __restrict__ w1h, __nv_bfloat16* __restrict__ w1l,
        __nv_bfloat16* __restrict__ w2h, __nv_bfloat16* __restrict__ w2l) {
    __shared__ float tile[32][33];
    int bid = blockIdx.x;
    const float* src; __nv_bfloat16 *dh, *dl;
    int K, N, ro, l, n0, k0;
    size_t sLs, dLs;
    if (bid < 27648) {
        int z = bid / 576;               // which*L + l
        int which = z / L_;  l = z - which * L_;
        int rem = bid % 576;
        n0 = (rem % 24) * 32;  k0 = (rem / 24) * 32;
        src = (which == 0) ? Wq : (which == 1) ? Wk : (which == 2) ? Wv : Wo;
        dh = (which < 3) ? qh : ohp;  dl = (which < 3) ? ql : olp;
        K = E_; N = E_; sLs = (size_t)E_*E_;
        dLs = (which < 3) ? (size_t)QKV*E_ : (size_t)E_*E_;
        ro = (which < 3) ? which * E_ : 0;
    } else if (bid < 55296) {
        int id = bid - 27648;
        l = id / 2304;  int rem = id % 2304;     // 96*24 tiles
        n0 = (rem % 96) * 32;  k0 = (rem / 96) * 32;
        src = W1; dh = w1h; dl = w1l;
        K = E_; N = F_; sLs = (size_t)E_*F_; dLs = (size_t)F_*E_; ro = 0;
    } else {
        int id = bid - 55296;
        l = id / 2304;  int rem = id % 2304;     // 24*96 tiles
        n0 = (rem % 24) * 32;  k0 = (rem / 24) * 32;
        src = W2; dh = w2h; dl = w2l;
        K = F_; N = E_; sLs = (size_t)F_*E_; dLs = (size_t)E_*F_; ro = 0;
    }

    int tx = threadIdx.x & 31, ty = threadIdx.x >> 5;
    const float* s = src + (size_t)l * sLs;
#pragma unroll
    for (int r = 0; r < 4; r++)
        tile[ty + r*8][tx] = s[(size_t)(k0 + ty + r*8) * N + n0 + tx];
    __syncthreads();
#pragma unroll
    for (int r = 0; r < 4; r++) {
        int n = n0 + ty + r*8, k = k0 + tx;
        float v = tile[tx][ty + r*8];
        __nv_bfloat16 h, lo; split_bf(v, h, lo);
        size_t di = (size_t)l * dLs + (size_t)(ro + n) * K + k;
        dh[di] = h; dl[di] = lo;
    }
}

// ==================== embedding + packb (merged: 4608 + 108 blocks) ==========
__global__ void embed_packb_k(const int* __restrict__ nt, const float* __restrict__ nif,
                              const int* __restrict__ ind, const int* __restrict__ outd,
                              const float* __restrict__ nemb, const float* __restrict__ iemb,
                              const float* __restrict__ oemb, float* __restrict__ x,
                              __nv_bfloat16* __restrict__ xh, __nv_bfloat16* __restrict__ xl,
                              const float* __restrict__ bq, const float* __restrict__ bk,
                              const float* __restrict__ bv, float* __restrict__ bo) {
    int bid = blockIdx.x;
    if (bid < 4608) {
        int idx = bid * 256 + threadIdx.x;
        int e = idx % E_, tok = idx / E_;
        int b = tok % B_, n = tok / B_;
        int bn = b*Nn + n;
        int t  = nt[bn];
        float v = nemb[t*E_+e] + iemb[ind[bn]*E_+e] + oemb[outd[bn]*E_+e] + nif[(size_t)bn*E_+e];
        x[idx] = v;
        __nv_bfloat16 h, lo; split_bf(v, h, lo);
        xh[idx] = h; xl[idx] = lo;
    } else {
        int idx = (bid - 4608) * 256 + threadIdx.x;
        if (idx >= L_*QKV) return;
        int n = idx % QKV, l = idx / QKV;
        float v;
        if      (n < E_)   v = bq[l*E_ + n];
        else if (n < 2*E_) v = bk[l*E_ + n - E_];
        else               v = bv[l*E_ + n - 2*E_];
        bo[idx] = v;
    }
}

// ==================== spatial bias (tiled) ====================
__global__ void __launch_bounds__(256)
bias_k(const int* __restrict__ sp, const float* __restrict__ ab,
       const float* __restrict__ se, const float* __restrict__ ser,
       float* __restrict__ bias) {
    int b = blockIdx.x, n0 = blockIdx.y * 32, m0 = blockIdx.z * 32;
    __shared__ int s1t[32][33];
    __shared__ int s2t[32][33];
    __shared__ float abt[32][33];
    int tid = threadIdx.x;
    for (int i = tid; i < 1024; i += 256) {
        int r = i >> 5, cc = i & 31;
        s1t[r][cc] = sp[((size_t)(b*Nn) + n0 + r) * Nn + m0 + cc];
        s2t[r][cc] = sp[((size_t)(b*Nn) + m0 + r) * Nn + n0 + cc];
        abt[r][cc] = ab[((size_t)(b*Nn) + n0 + r) * Nn + m0 + cc];
    }
    __syncthreads();
    for (int h = 0; h < H_; h++) {
        for (int i = tid; i < 1024; i += 256) {
            int r = i >> 5, cc = i & 31;
            float v = se[s1t[r][cc] * H_ + h] + ser[s2t[cc][r] * H_ + h] + abt[r][cc];
            bias[(((size_t)(b*H_ + h) * Nn) + n0 + r) * Nn + m0 + cc] = v;
        }
    }
}

// ==================== bf16x3 tensor-core GEMM (mma.sync + ldmatrix) ==========
#define RS   20
#define STG  30720
#define GSMT (3*STG)

#define GISSUE(t, s) do { \
    unsigned so_ = sb + (unsigned)(s)*STG; \
    unsigned da_ = so_ + arow*80u + ac0*16u; \
    const char* gah_ = Agh + (size_t)(t)*64 + ac0*16; \
    const char* gal_ = Agl + (size_t)(t)*64 + ac0*16; \
    CP_ASYNC16(da_, gah_); CP_ASYNC16(da_+16u, gah_+16); \
    CP_ASYNC16(da_+10240u, gal_); CP_ASYNC16(da_+10256u, gal_+16); \
    unsigned db_ = so_ + 20480u + brow*80u + bc*16u; \
    CP_ASYNC16(db_, Bgh + (size_t)(t)*64 + bc*16); \
    CP_ASYNC16(db_+5120u, Bgl + (size_t)(t)*64 + bc*16); \
} while (0)

template<int EPI>  // 0 = bias -> fp32 C;  1 = bias+gelu -> bf16 hi/lo Ch/Cl
__global__ void __launch_bounds__(256, 2)
mma_gemm(const __nv_bfloat16* __restrict__ Ah, const __nv_bfloat16* __restrict__ Al,
         const __nv_bfloat16* __restrict__ Wh, const __nv_bfloat16* __restrict__ Wl,
         const float* __restrict__ bias, float* __restrict__ C,
         __nv_bfloat16* __restrict__ Ch, __nv_bfloat16* __restrict__ Cl,
         int M, int K, int Nc, float scale) {
    extern __shared__ char sm[];
    unsigned sb = smem_u32(sm);
    int tid = threadIdx.x, wid = tid >> 5, lane = tid & 31;
    int q = lane & 3;
    int wm = (wid & 3) * 32, wn = (wid >> 2) * 32;
    int bm0 = blockIdx.y * 128, bn0 = blockIdx.x * 64;

    // cp.async producer mapping
    unsigned arow = tid >> 1;
    unsigned ac0  = (tid & 1) * 2;
    unsigned brow = tid >> 2;
    unsigned bc   = tid & 3;
    const char* Agh = (const char*)(Ah + (size_t)(bm0 + arow) * K);
    const char* Agl = (const char*)(Al + (size_t)(bm0 + arow) * K);
    const char* Bgh = (const char*)(Wh + (size_t)(bn0 + brow) * K);
    const char* Bgl = (const char*)(Wl + (size_t)(bn0 + brow) * K);

    // ldmatrix per-lane address offsets (relative to stage base)
    unsigned lsub = (unsigned)lane >> 3, lr = (unsigned)lane & 7;
    unsigned aoff = ((unsigned)wm + (lsub & 1) * 8 + lr) * 80u + (lsub >> 1) * 16u;
    unsigned boff = 20480u + ((unsigned)wn + (lsub >> 1) * 8 + lr) * 80u + (lsub & 1) * 16u;

    float acc[2][4][4];
#pragma unroll
    for (int i = 0; i < 2; i++)
#pragma unroll
        for (int j = 0; j < 4; j++)
#pragma unroll
            for (int c = 0; c < 4; c++) acc[i][j][c] = 0.f;

    int ntiles = K >> 5;
    GISSUE(0, 0); CP_COMMIT();
    GISSUE(1, 1); CP_COMMIT();

    for (int t = 0; t < ntiles; t++) {
        CP_WAIT1();
        __syncthreads();
        int tn = t + 2;
        if (tn < ntiles) { int s2 = tn % 3; GISSUE(tn, s2); }
        CP_COMMIT();

        unsigned stg = sb + (unsigned)(t % 3) * STG;
        unsigned aH = stg + aoff;            // A hi
        unsigned bH = stg + boff;            // B hi
#pragma unroll
        for (int kk = 0; kk < 2; kk++) {
            unsigned ko = (unsigned)kk * 32u;
            unsigned ah[2][4], al[2][4], bh[4][2], bl[4][2];
#pragma unroll
            for (int mt = 0; mt < 2; mt++) {
                unsigned a0 = aH + (unsigned)mt * 1280u + ko;
                LDMX4(ah[mt][0], ah[mt][1], ah[mt][2], ah[mt][3], a0);
                LDMX4(al[mt][0], al[mt][1], al[mt][2], al[mt][3], a0 + 10240u);
            }
#pragma unroll
            for (int np = 0; np < 2; np++) {
                unsigned b0 = bH + (unsigned)np * 1280u + ko;
                LDMX4(bh[2*np][0], bh[2*np][1], bh[2*np+1][0], bh[2*np+1][1], b0);
                LDMX4(bl[2*np][0], bl[2*np][1], bl[2*np+1][0], bl[2*np+1][1], b0 + 5120u);
            }
            // split-major issue: 8 independent acc chains per split term.
            // Per-acc contribution order stays hh -> lh -> hl (bitwise identical).
#pragma unroll
            for (int mt = 0; mt < 2; mt++)
#pragma unroll
                for (int nt = 0; nt < 4; nt++)
                    MMA_BF16(acc[mt][nt], ah[mt], bh[nt]);
#pragma unroll
            for (int mt = 0; mt < 2; mt++)
#pragma unroll
                for (int nt = 0; nt < 4; nt++)
                    MMA_BF16(acc[mt][nt], al[mt], bh[nt]);
#pragma unroll
            for (int mt = 0; mt < 2; mt++)
#pragma unroll
                for (int nt = 0; nt < 4; nt++)
                    MMA_BF16(acc[mt][nt], ah[mt], bl[nt]);
        }
    }

    int g = lane >> 2;
#pragma unroll
    for (int mt = 0; mt < 2; mt++) {
#pragma unroll
        for (int nt = 0; nt < 4; nt++) {
            int col = bn0 + wn + nt*8 + 2*q;
            int r0  = bm0 + wm + mt*16 + g;
            float blo = bias[col], bhi = bias[col + 1];
            float v00 = (acc[mt][nt][0] + blo) * scale;
            float v01 = (acc[mt][nt][1] + bhi) * scale;
            float v10 = (acc[mt][nt][2] + blo) * scale;
            float v11 = (acc[mt][nt][3] + bhi) * scale;
            if (EPI == 0) {
                *(float2*)&C[(size_t)r0       * Nc + col] = make_float2(v00, v01);
                *(float2*)&C[(size_t)(r0 + 8) * Nc + col] = make_float2(v10, v11);
            } else {
                v00 = gelu_f(v00); v01 = gelu_f(v01);
                v10 = gelu_f(v10); v11 = gelu_f(v11);
                __nv_bfloat16 h0, l0, h1, l1;
                split_bf(v00, h0, l0); split_bf(v01, h1, l1);
                { __nv_bfloat162 hp; hp.x = h0; hp.y = h1;
                  *(__nv_bfloat162*)&Ch[(size_t)r0 * Nc + col] = hp;
                  __nv_bfloat162 lp; lp.x = l0; lp.y = l1;
                  *(__nv_bfloat162*)&Cl[(size_t)r0 * Nc + col] = lp; }
                split_bf(v10, h0, l0); split_bf(v11, h1, l1);
                { __nv_bfloat162 hp; hp.x = h0; hp.y = h1;
                  *(__nv_bfloat162*)&Ch[(size_t)(r0 + 8) * Nc + col] = hp;
                  __nv_bfloat162 lp; lp.x = l0; lp.y = l1;
                  *(__nv_bfloat162*)&Cl[(size_t)(r0 + 8) * Nc + col] = lp; }
            }
        }
    }
}

// ==================== fused attention: scores+bias+mask+softmax+PV ===========
#define FA_KD   0
#define FA_VD   (24*385)
#define FA_QS   (2*24*385)
#define FA_MK   (2*24*385 + 384*25)
#define FA_SMEM ((2*24*385 + 384*25 + 384) * 4)

__global__ void __launch_bounds__(256, 1)
fattn_k(const float* __restrict__ qkv, const float* __restrict__ bias,
        const int* __restrict__ nt,
        __nv_bfloat16* __restrict__ oh, __nv_bfloat16* __restrict__ ol) {
    extern __shared__ float fs[];
    float* kd = fs + FA_KD;
    float* vd = fs + FA_VD;
    float* qs = fs + FA_QS;
    float* mk = fs + FA_MK;
    int bh = blockIdx.x;
    int b = bh >> 5, h = bh & 31;
    int tid = threadIdx.x, w = tid >> 5, lane = tid & 31;
    const float scaling = 0.20412414523193154f;   // 24^-0.5

    for (int i = tid; i < 384*24; i += 256) {
        int m = i / 24, d = i % 24;
        size_t base = ((size_t)m*B_ + b)*QKV + h*D_ + d;
        qs[m*25 + d]  = qkv[base] * scaling;
        kd[d*385 + m] = qkv[base + E_];
        vd[d*385 + m] = qkv[base + 2*E_];
    }
    for (int i = tid; i < 384; i += 256)
        mk[i] = (nt[b*Nn + i] == 0) ? -1e30f : 0.f;
    __syncthreads();

    for (int g = 0; g < 12; g++) {
        int r0 = g*32 + w*4;
        float sv[4][12];
#pragma unroll
        for (int r = 0; r < 4; r++)
#pragma unroll
            for (int j = 0; j < 12; j++) sv[r][j] = 0.f;

#pragma unroll
        for (int db = 0; db < 4; db++) {
            float qreg[4][6];
#pragma unroll
            for (int r = 0; r < 4; r++)
#pragma unroll
                for (int dd = 0; dd < 6; dd++)
                    qreg[r][dd] = qs[(r0 + r)*25 + db*6 + dd];
#pragma unroll
            for (int j = 0; j < 12; j++) {
                int m = lane + 32*j;
#pragma unroll
                for (int dd = 0; dd < 6; dd++) {
                    float kv = kd[(db*6 + dd)*385 + m];
#pragma unroll
                    for (int r = 0; r < 4; r++)
                        sv[r][j] = fmaf(qreg[r][dd], kv, sv[r][j]);
                }
            }
        }

#pragma unroll
        for (int r = 0; r < 4; r++) {
            int n = r0 + r;
            const float* brow = bias + ((size_t)bh*Nn + n)*Nn;
            float mx = -3.4e38f;
#pragma unroll
            for (int j = 0; j < 12; j++) {
                int m = lane + 32*j;
                float val = sv[r][j] + brow[m] + mk[m];
                sv[r][j] = val; mx = fmaxf(mx, val);
            }
            for (int o = 16; o; o >>= 1) mx = fmaxf(mx, __shfl_xor_sync(0xffffffffu, mx, o));
            float sum = 0.f;
#pragma unroll
            for (int j = 0; j < 12; j++) {
                float e = __expf(sv[r][j] - mx); sv[r][j] = e; sum += e;
            }
            for (int o = 16; o; o >>= 1) sum += __shfl_xor_sync(0xffffffffu, sum, o);
            float inv = 1.f / sum;
#pragma unroll
            for (int j = 0; j < 12; j++) sv[r][j] *= inv;
        }

        float acc[4][24];
#pragma unroll
        for (int r = 0; r < 4; r++)
#pragma unroll
            for (int d = 0; d < 24; d++) acc[r][d] = 0.f;
#pragma unroll
        for (int j = 0; j < 12; j++) {
            int m = lane + 32*j;
#pragma unroll
            for (int d = 0; d < 24; d++) {
                float v = vd[d*385 + m];
#pragma unroll
                for (int r = 0; r < 4; r++)
                    acc[r][d] = fmaf(sv[r][j], v, acc[r][d]);
            }
        }

#pragma unroll
        for (int r = 0; r < 4; r++) {
            int n = r0 + r;
            float myv = 0.f;
#pragma unroll
            for (int d = 0; d < 24; d++) {
                float t = acc[r][d];
                for (int o = 16; o; o >>= 1) t += __shfl_xor_sync(0xffffffffu, t, o);
                if (lane == d) myv = t;
            }
            if (lane < 24) {
                size_t idx = ((size_t)n*B_ + b)*E_ + h*D_ + lane;
                __nv_bfloat16 hv, lv; split_bf(myv, hv, lv);
                oh[idx] = hv; ol[idx] = lv;
            }
        }
    }
}

// ==================== residual add + LayerNorm (+ bf16 hi/lo out) ============
__global__ void __launch_bounds__(256)
ln_k(const float* __restrict__ x, const float* __restrict__ a,
     const float* __restrict__ s, const float* __restrict__ bb,
     float* __restrict__ out,
     __nv_bfloat16* __restrict__ oh, __nv_bfloat16* __restrict__ ol) {
    __shared__ float r1[8], r2[8];
    int t = blockIdx.x, tid = threadIdx.x;
    const float* xp = x + (size_t)t * E_;
    const float* ap = a + (size_t)t * E_;
    float v[3]; float sum = 0.f;
#pragma unroll
    for (int i = 0; i < 3; i++) { int e = tid + (i << 8); v[i] = xp[e] + ap[e]; sum += v[i]; }
    for (int o = 16; o; o >>= 1) sum += __shfl_xor_sync(0xffffffffu, sum, o);
    if ((tid & 31) == 0) r1[tid >> 5] = sum;
    __syncthreads();
    sum = 0.f;
#pragma unroll
    for (int w = 0; w < 8; w++) sum += r1[w];
    float mu = sum * (1.f / 768.f);
    float var = 0.f;
#pragma unroll
    for (int i = 0; i < 3; i++) { float d = v[i] - mu; var += d * d; }
    for (int o = 16; o; o >>= 1) var += __shfl_xor_sync(0xffffffffu, var, o);
    if ((tid & 31) == 0) r2[tid >> 5] = var;
    __syncthreads();
    var = 0.f;
#pragma unroll
    for (int w = 0; w < 8; w++) var += r2[w];
    float rstd = rsqrtf(var * (1.f / 768.f) + 1e-5f);
#pragma unroll
    for (int i = 0; i < 3; i++) {
        int e = tid + (i << 8);
        float o = (v[i] - mu) * rstd * s[e] + bb[e];
        out[(size_t)t * E_ + e] = o;
        __nv_bfloat16 hh, ll; split_bf(o, hh, ll);
        oh[(size_t)t * E_ + e] = hh; ol[(size_t)t * E_ + e] = ll;
    }
}

// ==================== orchestration ====================
extern "C" void kernel_launch(void* const* d_in, const int* in_sizes, int n_in,
                              void* d_out, int out_size) {
    const int*   nt    = (const int*)  d_in[0];
    const float* nif   = (const float*)d_in[1];
    const int*   ind   = (const int*)  d_in[2];
    const int*   outd  = (const int*)  d_in[3];
    const float* ab    = (const float*)d_in[4];
    const int*   sp    = (const int*)  d_in[5];
    const float* nemb  = (const float*)d_in[6];
    const float* iemb  = (const float*)d_in[7];
    const float* oemb  = (const float*)d_in[8];
    const float* se    = (const float*)d_in[9];
    const float* ser   = (const float*)d_in[10];
    const float* Wq    = (const float*)d_in[11];
    const float* bq    = (const float*)d_in[12];
    const float* Wk    = (const float*)d_in[13];
    const float* bk    = (const float*)d_in[14];
    const float* Wv    = (const float*)d_in[15];
    const float* bv    = (const float*)d_in[16];
    const float* Wo    = (const float*)d_in[17];
    const float* bo    = (const float*)d_in[18];
    const float* W1    = (const float*)d_in[19];
    const float* b1    = (const float*)d_in[20];
    const float* W2    = (const float*)d_in[21];
    const float* b2    = (const float*)d_in[22];
    const float* ln1s  = (const float*)d_in[23];
    const float* ln1b  = (const float*)d_in[24];
    const float* ln2s  = (const float*)d_in[25];
    const float* ln2b  = (const float*)d_in[26];
    float* out = (float*)d_out;

    float *x, *tmp, *qkv, *bias, *bqkv;
    __nv_bfloat16 *xh, *xl, *ch, *cl, *hh, *hl;
    __nv_bfloat16 *wqkvh, *wqkvl, *woh, *wol, *w1h, *w1l, *w2h, *w2l;
    cudaGetSymbolAddress((void**)&x,    g_x);
    cudaGetSymbolAddress((void**)&tmp,  g_tmp);
    cudaGetSymbolAddress((void**)&qkv,  g_qkv);
    cudaGetSymbolAddress((void**)&bias, g_bias);
    cudaGetSymbolAddress((void**)&bqkv, g_bqkv);
    cudaGetSymbolAddress((void**)&xh,   g_xh);
    cudaGetSymbolAddress((void**)&xl,   g_xl);
    cudaGetSymbolAddress((void**)&ch,   g_ch);
    cudaGetSymbolAddress((void**)&cl,   g_cl);
    cudaGetSymbolAddress((void**)&hh,   g_hh);
    cudaGetSymbolAddress((void**)&hl,   g_hl);
    cudaGetSymbolAddress((void**)&wqkvh, g_wqkvh);
    cudaGetSymbolAddress((void**)&wqkvl, g_wqkvl);
    cudaGetSymbolAddress((void**)&woh,   g_woh);
    cudaGetSymbolAddress((void**)&wol,   g_wol);
    cudaGetSymbolAddress((void**)&w1h,   g_w1h);
    cudaGetSymbolAddress((void**)&w1l,   g_w1l);
    cudaGetSymbolAddress((void**)&w2h,   g_w2h);
    cudaGetSymbolAddress((void**)&w2l,   g_w2l);

    cudaFuncSetAttribute(mma_gemm<0>, cudaFuncAttributeMaxDynamicSharedMemorySize, GSMT);
    cudaFuncSetAttribute(mma_gemm<1>, cudaFuncAttributeMaxDynamicSharedMemorySize, GSMT);
    cudaFuncSetAttribute(fattn_k, cudaFuncAttributeMaxDynamicSharedMemorySize, FA_SMEM);

    // ---- prepass: 3 launches, so our idx 3 == first QKV GEMM (profiled slot) ----
    trall_k<<<TRALL_BLOCKS, 256>>>(Wq, Wk, Wv, Wo, W1, W2,
                                   wqkvh, wqkvl, woh, wol,
                                   w1h, w1l, w2h, w2l);                     // idx 0
    embed_packb_k<<<4608 + 108, 256>>>(nt, nif, ind, outd, nemb, iemb, oemb,
                                       x, xh, xl, bq, bk, bv, bqkv);        // idx 1
    bias_k<<<dim3(B_, Nn/32, Nn/32), 256>>>(sp, ab, se, ser, bias);         // idx 2

    dim3 gQKV(QKV/64, T_/128);     // (36, 12)
    dim3 gE(E_/64, T_/128);        // (12, 12)
    dim3 gF1(F_/64, T_/128);       // (48, 12)

    for (int l = 0; l < L_; l++) {
        mma_gemm<0><<<gQKV, 256, GSMT>>>(xh, xl,
            wqkvh + (size_t)l*QKV*E_, wqkvl + (size_t)l*QKV*E_,
            bqkv + l*QKV, qkv, hh, hl, T_, E_, QKV, 1.f);                   // idx 3 (l=0)

        fattn_k<<<B_*H_, 256, FA_SMEM>>>(qkv, bias, nt, ch, cl);

        mma_gemm<0><<<gE, 256, GSMT>>>(ch, cl,
            woh + (size_t)l*E_*E_, wol + (size_t)l*E_*E_,
            bo + l*E_, tmp, hh, hl, T_, E_, E_, 1.f);
        ln_k<<<T_, 256>>>(x, tmp, ln1s + l*E_, ln1b + l*E_, x, xh, xl);

        mma_gemm<1><<<gF1, 256, GSMT>>>(xh, xl,
            w1h + (size_t)l*F_*E_, w1l + (size_t)l*F_*E_,
            b1 + l*F_, tmp, hh, hl, T_, E_, F_, 1.f);
        mma_gemm<0><<<gE, 256, GSMT>>>(hh, hl,
            w2h + (size_t)l*E_*F_, w2l + (size_t)l*E_*F_,
            b2 + l*E_, tmp, hh, hl, T_, F_, E_, 1.f);

        float* dst = (l == L_-1) ? out : x;
        ln_k<<<T_, 256>>>(x, tmp, ln2s + l*E_, ln2b + l*E_, dst, xh, xl);
    }
}

// round 14
// speedup vs baseline: 1.0024x; 1.0024x over previous
#include <cuda_runtime.h>
#include <cuda_bf16.h>
#include <math.h>

#define B_  4
#define Nn  384
#define E_  768
#define H_  32
#define F_  3072
#define L_  12
#define S_  512
#define D_  24
#define T_  (B_*Nn)          // 1536 tokens
#define QKV 2304             // 3*E

// -------------------- scratch (static device allocations) --------------------
__device__ float g_x   [T_*E_];
__device__ float g_tmp [T_*E_];
__device__ float g_qkv [T_*QKV];
__device__ float g_bias[B_*H_*Nn*Nn];
__device__ float g_bqkv[L_*QKV];
// bf16 hi/lo activation buffers
__device__ __nv_bfloat16 g_xh[T_*E_],  g_xl[T_*E_];
__device__ __nv_bfloat16 g_ch[T_*E_],  g_cl[T_*E_];
__device__ __nv_bfloat16 g_hh[T_*F_],  g_hl[T_*F_];
// bf16 hi/lo transposed weights, [l][n][k]
__device__ __nv_bfloat16 g_wqkvh[(size_t)L_*QKV*E_], g_wqkvl[(size_t)L_*QKV*E_];
__device__ __nv_bfloat16 g_woh  [(size_t)L_*E_*E_],  g_wol  [(size_t)L_*E_*E_];
__device__ __nv_bfloat16 g_w1h  [(size_t)L_*F_*E_],  g_w1l  [(size_t)L_*F_*E_];
__device__ __nv_bfloat16 g_w2h  [(size_t)L_*E_*F_],  g_w2l  [(size_t)L_*E_*F_];

// ==================== helpers ====================
__device__ __forceinline__ float gelu_f(float x) {
    return 0.5f * x * (1.0f + tanhf(0.7978845608028654f * (x + 0.044715f * x * x * x)));
}
__device__ __forceinline__ unsigned smem_u32(const void* p) {
    return (unsigned)__cvta_generic_to_shared(p);
}
#define CP_ASYNC16(dst, src) \
    asm volatile("cp.async.cg.shared.global [%0], [%1], 16;\n" :: "r"(dst), "l"(src) : "memory")
#define CP_COMMIT() asm volatile("cp.async.commit_group;\n" ::: "memory")
#define CP_WAIT1()  asm volatile("cp.async.wait_group 1;\n" ::: "memory")

#define MMA_BF16(acc, a, b) \
    asm volatile("mma.sync.aligned.m16n8k16.row.col.f32.bf16.bf16.f32 " \
        "{%0,%1,%2,%3}, {%4,%5,%6,%7}, {%8,%9}, {%0,%1,%2,%3};" \
        : "+f"((acc)[0]), "+f"((acc)[1]), "+f"((acc)[2]), "+f"((acc)[3]) \
        : "r"((a)[0]), "r"((a)[1]), "r"((a)[2]), "r"((a)[3]), "r"((b)[0]), "r"((b)[1]))

#define LDMX4(r0, r1, r2, r3, addr) \
    asm volatile("ldmatrix.sync.aligned.m8n8.x4.shared.b16 {%0,%1,%2,%3}, [%4];" \
        : "=r"(r0), "=r"(r1), "=r"(r2), "=r"(r3) : "r"(addr))

__device__ __forceinline__ void split_bf(float v, __nv_bfloat16& h, __nv_bfloat16& l) {
    h = __float2bfloat16_rn(v);
    l = __float2bfloat16_rn(v - __bfloat162float(h));
}

// ==================== ALL weight transposes in ONE kernel ====================
#define TRALL_BLOCKS 82944
__global__ void __launch_bounds__(256)
trall_k(const float* __restrict__ Wq, const float* __restrict__ Wk,
        const float* __restrict__ Wv, const float* __restrict__ Wo,
        const float* __restrict__ W1, const float* __restrict__ W2,
        __nv_bfloat16* __restrict__ qh, __nv_bfloat16* __restrict__ ql,
        __nv_bfloat16* __restrict__ ohp, __nv_bfloat16* __restrict__ olp,
        __nv_bfloat16* __restrict__ w1h, __nv_bfloat16* __restrict__ w1l,
        __nv_bfloat16* __restrict__ w2h, __nv_bfloat16* __restrict__ w2l) {
    __shared__ float tile[32][33];
    int bid = blockIdx.x;
    const float* src; __nv_bfloat16 *dh, *dl;
    int K, N, ro, l, n0, k0;
    size_t sLs, dLs;
    if (bid < 27648) {
        int z = bid / 576;
        int which = z / L_;  l = z - which * L_;
        int rem = bid % 576;
        n0 = (rem % 24) * 32;  k0 = (rem / 24) * 32;
        src = (which == 0) ? Wq : (which == 1) ? Wk : (which == 2) ? Wv : Wo;
        dh = (which < 3) ? qh : ohp;  dl = (which < 3) ? ql : olp;
        K = E_; N = E_; sLs = (size_t)E_*E_;
        dLs = (which < 3) ? (size_t)QKV*E_ : (size_t)E_*E_;
        ro = (which < 3) ? which * E_ : 0;
    } else if (bid < 55296) {
        int id = bid - 27648;
        l = id / 2304;  int rem = id % 2304;
        n0 = (rem % 96) * 32;  k0 = (rem / 96) * 32;
        src = W1; dh = w1h; dl = w1l;
        K = E_; N = F_; sLs = (size_t)E_*F_; dLs = (size_t)F_*E_; ro = 0;
    } else {
        int id = bid - 55296;
        l = id / 2304;  int rem = id % 2304;
        n0 = (rem % 24) * 32;  k0 = (rem / 24) * 32;
        src = W2; dh = w2h; dl = w2l;
        K = F_; N = E_; sLs = (size_t)F_*E_; dLs = (size_t)E_*F_; ro = 0;
    }

    int tx = threadIdx.x & 31, ty = threadIdx.x >> 5;
    const float* s = src + (size_t)l * sLs;
#pragma unroll
    for (int r = 0; r < 4; r++)
        tile[ty + r*8][tx] = s[(size_t)(k0 + ty + r*8) * N + n0 + tx];
    __syncthreads();
#pragma unroll
    for (int r = 0; r < 4; r++) {
        int n = n0 + ty + r*8, k = k0 + tx;
        float v = tile[tx][ty + r*8];
        __nv_bfloat16 h, lo; split_bf(v, h, lo);
        size_t di = (size_t)l * dLs + (size_t)(ro + n) * K + k;
        dh[di] = h; dl[di] = lo;
    }
}

// ==================== embedding + packb ====================
__global__ void embed_packb_k(const int* __restrict__ nt, const float* __restrict__ nif,
                              const int* __restrict__ ind, const int* __restrict__ outd,
                              const float* __restrict__ nemb, const float* __restrict__ iemb,
                              const float* __restrict__ oemb, float* __restrict__ x,
                              __nv_bfloat16* __restrict__ xh, __nv_bfloat16* __restrict__ xl,
                              const float* __restrict__ bq, const float* __restrict__ bk,
                              const float* __restrict__ bv, float* __restrict__ bo) {
    int bid = blockIdx.x;
    if (bid < 4608) {
        int idx = bid * 256 + threadIdx.x;
        int e = idx % E_, tok = idx / E_;
        int b = tok % B_, n = tok / B_;
        int bn = b*Nn + n;
        int t  = nt[bn];
        float v = nemb[t*E_+e] + iemb[ind[bn]*E_+e] + oemb[outd[bn]*E_+e] + nif[(size_t)bn*E_+e];
        x[idx] = v;
        __nv_bfloat16 h, lo; split_bf(v, h, lo);
        xh[idx] = h; xl[idx] = lo;
    } else {
        int idx = (bid - 4608) * 256 + threadIdx.x;
        if (idx >= L_*QKV) return;
        int n = idx % QKV, l = idx / QKV;
        float v;
        if      (n < E_)   v = bq[l*E_ + n];
        else if (n < 2*E_) v = bk[l*E_ + n - E_];
        else               v = bv[l*E_ + n - 2*E_];
        bo[idx] = v;
    }
}

// ==================== spatial bias (tiled) ====================
__global__ void __launch_bounds__(256)
bias_k(const int* __restrict__ sp, const float* __restrict__ ab,
       const float* __restrict__ se, const float* __restrict__ ser,
       float* __restrict__ bias) {
    int b = blockIdx.x, n0 = blockIdx.y * 32, m0 = blockIdx.z * 32;
    __shared__ int s1t[32][33];
    __shared__ int s2t[32][33];
    __shared__ float abt[32][33];
    int tid = threadIdx.x;
    for (int i = tid; i < 1024; i += 256) {
        int r = i >> 5, cc = i & 31;
        s1t[r][cc] = sp[((size_t)(b*Nn) + n0 + r) * Nn + m0 + cc];
        s2t[r][cc] = sp[((size_t)(b*Nn) + m0 + r) * Nn + n0 + cc];
        abt[r][cc] = ab[((size_t)(b*Nn) + n0 + r) * Nn + m0 + cc];
    }
    __syncthreads();
    for (int h = 0; h < H_; h++) {
        for (int i = tid; i < 1024; i += 256) {
            int r = i >> 5, cc = i & 31;
            float v = se[s1t[r][cc] * H_ + h] + ser[s2t[cc][r] * H_ + h] + abt[r][cc];
            bias[(((size_t)(b*H_ + h) * Nn) + n0 + r) * Nn + m0 + cc] = v;
        }
    }
}

// ==================== bf16x3 GEMM, 128x64 tile (QKV / FFN1) ==================
#define RS   20
#define STG  30720
#define GSMT (3*STG)

#define GISSUE(t, s) do { \
    unsigned so_ = sb + (unsigned)(s)*STG; \
    unsigned da_ = so_ + arow*80u + ac0*16u; \
    const char* gah_ = Agh + (size_t)(t)*64 + ac0*16; \
    const char* gal_ = Agl + (size_t)(t)*64 + ac0*16; \
    CP_ASYNC16(da_, gah_); CP_ASYNC16(da_+16u, gah_+16); \
    CP_ASYNC16(da_+10240u, gal_); CP_ASYNC16(da_+10256u, gal_+16); \
    unsigned db_ = so_ + 20480u + brow*80u + bc*16u; \
    CP_ASYNC16(db_, Bgh + (size_t)(t)*64 + bc*16); \
    CP_ASYNC16(db_+5120u, Bgl + (size_t)(t)*64 + bc*16); \
} while (0)

template<int EPI>  // 0 = bias -> fp32 C;  1 = bias+gelu -> bf16 hi/lo Ch/Cl
__global__ void __launch_bounds__(256, 2)
mma_gemm(const __nv_bfloat16* __restrict__ Ah, const __nv_bfloat16* __restrict__ Al,
         const __nv_bfloat16* __restrict__ Wh, const __nv_bfloat16* __restrict__ Wl,
         const float* __restrict__ bias, float* __restrict__ C,
         __nv_bfloat16* __restrict__ Ch, __nv_bfloat16* __restrict__ Cl,
         int M, int K, int Nc, float scale) {
    extern __shared__ char sm[];
    unsigned sb = smem_u32(sm);
    int tid = threadIdx.x, wid = tid >> 5, lane = tid & 31;
    int q = lane & 3;
    int wm = (wid & 3) * 32, wn = (wid >> 2) * 32;
    int bm0 = blockIdx.y * 128, bn0 = blockIdx.x * 64;

    unsigned arow = tid >> 1;
    unsigned ac0  = (tid & 1) * 2;
    unsigned brow = tid >> 2;
    unsigned bc   = tid & 3;
    const char* Agh = (const char*)(Ah + (size_t)(bm0 + arow) * K);
    const char* Agl = (const char*)(Al + (size_t)(bm0 + arow) * K);
    const char* Bgh = (const char*)(Wh + (size_t)(bn0 + brow) * K);
    const char* Bgl = (const char*)(Wl + (size_t)(bn0 + brow) * K);

    unsigned lsub = (unsigned)lane >> 3, lr = (unsigned)lane & 7;
    unsigned aoff = ((unsigned)wm + (lsub & 1) * 8 + lr) * 80u + (lsub >> 1) * 16u;
    unsigned boff = 20480u + ((unsigned)wn + (lsub >> 1) * 8 + lr) * 80u + (lsub & 1) * 16u;

    float acc[2][4][4];
#pragma unroll
    for (int i = 0; i < 2; i++)
#pragma unroll
        for (int j = 0; j < 4; j++)
#pragma unroll
            for (int c = 0; c < 4; c++) acc[i][j][c] = 0.f;

    int ntiles = K >> 5;
    GISSUE(0, 0); CP_COMMIT();
    GISSUE(1, 1); CP_COMMIT();

    for (int t = 0; t < ntiles; t++) {
        CP_WAIT1();
        __syncthreads();
        int tn = t + 2;
        if (tn < ntiles) { int s2 = tn % 3; GISSUE(tn, s2); }
        CP_COMMIT();

        unsigned stg = sb + (unsigned)(t % 3) * STG;
        unsigned aH = stg + aoff;
        unsigned bH = stg + boff;
#pragma unroll
        for (int kk = 0; kk < 2; kk++) {
            unsigned ko = (unsigned)kk * 32u;
            unsigned ah[2][4], al[2][4], bh[4][2], bl[4][2];
#pragma unroll
            for (int mt = 0; mt < 2; mt++) {
                unsigned a0 = aH + (unsigned)mt * 1280u + ko;
                LDMX4(ah[mt][0], ah[mt][1], ah[mt][2], ah[mt][3], a0);
                LDMX4(al[mt][0], al[mt][1], al[mt][2], al[mt][3], a0 + 10240u);
            }
#pragma unroll
            for (int np = 0; np < 2; np++) {
                unsigned b0 = bH + (unsigned)np * 1280u + ko;
                LDMX4(bh[2*np][0], bh[2*np][1], bh[2*np+1][0], bh[2*np+1][1], b0);
                LDMX4(bl[2*np][0], bl[2*np][1], bl[2*np+1][0], bl[2*np+1][1], b0 + 5120u);
            }
#pragma unroll
            for (int mt = 0; mt < 2; mt++)
#pragma unroll
                for (int nt = 0; nt < 4; nt++)
                    MMA_BF16(acc[mt][nt], ah[mt], bh[nt]);
#pragma unroll
            for (int mt = 0; mt < 2; mt++)
#pragma unroll
                for (int nt = 0; nt < 4; nt++)
                    MMA_BF16(acc[mt][nt], al[mt], bh[nt]);
#pragma unroll
            for (int mt = 0; mt < 2; mt++)
#pragma unroll
                for (int nt = 0; nt < 4; nt++)
                    MMA_BF16(acc[mt][nt], ah[mt], bl[nt]);
        }
    }

    int g = lane >> 2;
#pragma unroll
    for (int mt = 0; mt < 2; mt++) {
#pragma unroll
        for (int nt = 0; nt < 4; nt++) {
            int col = bn0 + wn + nt*8 + 2*q;
            int r0  = bm0 + wm + mt*16 + g;
            float blo = bias[col], bhi = bias[col + 1];
            float v00 = (acc[mt][nt][0] + blo) * scale;
            float v01 = (acc[mt][nt][1] + bhi) * scale;
            float v10 = (acc[mt][nt][2] + blo) * scale;
            float v11 = (acc[mt][nt][3] + bhi) * scale;
            if (EPI == 0) {
                *(float2*)&C[(size_t)r0       * Nc + col] = make_float2(v00, v01);
                *(float2*)&C[(size_t)(r0 + 8) * Nc + col] = make_float2(v10, v11);
            } else {
                v00 = gelu_f(v00); v01 = gelu_f(v01);
                v10 = gelu_f(v10); v11 = gelu_f(v11);
                __nv_bfloat16 h0, l0, h1, l1;
                split_bf(v00, h0, l0); split_bf(v01, h1, l1);
                { __nv_bfloat162 hp; hp.x = h0; hp.y = h1;
                  *(__nv_bfloat162*)&Ch[(size_t)r0 * Nc + col] = hp;
                  __nv_bfloat162 lp; lp.x = l0; lp.y = l1;
                  *(__nv_bfloat162*)&Cl[(size_t)r0 * Nc + col] = lp; }
                split_bf(v10, h0, l0); split_bf(v11, h1, l1);
                { __nv_bfloat162 hp; hp.x = h0; hp.y = h1;
                  *(__nv_bfloat162*)&Ch[(size_t)(r0 + 8) * Nc + col] = hp;
                  __nv_bfloat162 lp; lp.x = l0; lp.y = l1;
                  *(__nv_bfloat162*)&Cl[(size_t)(r0 + 8) * Nc + col] = lp; }
            }
        }
    }
}

// ==================== bf16x3 GEMM, 64x64 tile (O-proj / FFN2) ================
// 128 threads = 4 warps (2m x 2n), warp tile 32x32. 3-stage, 20KB/stage.
// smem stage: Ah 5120 | Al 5120 | Bh 5120 | Bl 5120
#define STG64  20480
#define GSMT64 (3*STG64)

#define GISSUE64(t, s) do { \
    unsigned so_ = sb + (unsigned)(s)*STG64; \
    unsigned da_ = so_ + arow*80u + ac0*16u; \
    const char* gah_ = Agh + (size_t)(t)*64 + ac0*16; \
    const char* gal_ = Agl + (size_t)(t)*64 + ac0*16; \
    CP_ASYNC16(da_, gah_); CP_ASYNC16(da_+16u, gah_+16); \
    CP_ASYNC16(da_+5120u, gal_); CP_ASYNC16(da_+5136u, gal_+16); \
    unsigned db_ = so_ + 10240u + arow*80u + ac0*16u; \
    const char* gbh_ = Bgh + (size_t)(t)*64 + ac0*16; \
    const char* gbl_ = Bgl + (size_t)(t)*64 + ac0*16; \
    CP_ASYNC16(db_, gbh_); CP_ASYNC16(db_+16u, gbh_+16); \
    CP_ASYNC16(db_+5120u, gbl_); CP_ASYNC16(db_+5136u, gbl_+16); \
} while (0)

__global__ void __launch_bounds__(128, 3)
mma_gemm64(const __nv_bfloat16* __restrict__ Ah, const __nv_bfloat16* __restrict__ Al,
           const __nv_bfloat16* __restrict__ Wh, const __nv_bfloat16* __restrict__ Wl,
           const float* __restrict__ bias, float* __restrict__ C,
           int M, int K, int Nc) {
    extern __shared__ char sm[];
    unsigned sb = smem_u32(sm);
    int tid = threadIdx.x, wid = tid >> 5, lane = tid & 31;
    int q = lane & 3;
    int wm = (wid & 1) * 32, wn = (wid >> 1) * 32;
    int bm0 = blockIdx.y * 64, bn0 = blockIdx.x * 64;

    unsigned arow = tid >> 1;        // 0..63 (rows for BOTH A and B tiles)
    unsigned ac0  = (tid & 1) * 2;   // chunk 0 or 2
    const char* Agh = (const char*)(Ah + (size_t)(bm0 + arow) * K);
    const char* Agl = (const char*)(Al + (size_t)(bm0 + arow) * K);
    const char* Bgh = (const char*)(Wh + (size_t)(bn0 + arow) * K);
    const char* Bgl = (const char*)(Wl + (size_t)(bn0 + arow) * K);

    unsigned lsub = (unsigned)lane >> 3, lr = (unsigned)lane & 7;
    unsigned aoff = ((unsigned)wm + (lsub & 1) * 8 + lr) * 80u + (lsub >> 1) * 16u;
    unsigned boff = 10240u + ((unsigned)wn + (lsub >> 1) * 8 + lr) * 80u + (lsub & 1) * 16u;

    float acc[2][4][4];
#pragma unroll
    for (int i = 0; i < 2; i++)
#pragma unroll
        for (int j = 0; j < 4; j++)
#pragma unroll
            for (int c = 0; c < 4; c++) acc[i][j][c] = 0.f;

    int ntiles = K >> 5;
    GISSUE64(0, 0); CP_COMMIT();
    GISSUE64(1, 1); CP_COMMIT();

    for (int t = 0; t < ntiles; t++) {
        CP_WAIT1();
        __syncthreads();
        int tn = t + 2;
        if (tn < ntiles) { int s2 = tn % 3; GISSUE64(tn, s2); }
        CP_COMMIT();

        unsigned stg = sb + (unsigned)(t % 3) * STG64;
        unsigned aH = stg + aoff;
        unsigned bH = stg + boff;
#pragma unroll
        for (int kk = 0; kk < 2; kk++) {
            unsigned ko = (unsigned)kk * 32u;
            unsigned ah[2][4], al[2][4], bh[4][2], bl[4][2];
#pragma unroll
            for (int mt = 0; mt < 2; mt++) {
                unsigned a0 = aH + (unsigned)mt * 1280u + ko;
                LDMX4(ah[mt][0], ah[mt][1], ah[mt][2], ah[mt][3], a0);
                LDMX4(al[mt][0], al[mt][1], al[mt][2], al[mt][3], a0 + 5120u);
            }
#pragma unroll
            for (int np = 0; np < 2; np++) {
                unsigned b0 = bH + (unsigned)np * 1280u + ko;
                LDMX4(bh[2*np][0], bh[2*np][1], bh[2*np+1][0], bh[2*np+1][1], b0);
                LDMX4(bl[2*np][0], bl[2*np][1], bl[2*np+1][0], bl[2*np+1][1], b0 + 5120u);
            }
#pragma unroll
            for (int mt = 0; mt < 2; mt++)
#pragma unroll
                for (int nt = 0; nt < 4; nt++)
                    MMA_BF16(acc[mt][nt], ah[mt], bh[nt]);
#pragma unroll
            for (int mt = 0; mt < 2; mt++)
#pragma unroll
                for (int nt = 0; nt < 4; nt++)
                    MMA_BF16(acc[mt][nt], al[mt], bh[nt]);
#pragma unroll
            for (int mt = 0; mt < 2; mt++)
#pragma unroll
                for (int nt = 0; nt < 4; nt++)
                    MMA_BF16(acc[mt][nt], ah[mt], bl[nt]);
        }
    }

    int g = lane >> 2;
#pragma unroll
    for (int mt = 0; mt < 2; mt++) {
#pragma unroll
        for (int nt = 0; nt < 4; nt++) {
            int col = bn0 + wn + nt*8 + 2*q;
            int r0  = bm0 + wm + mt*16 + g;
            float blo = bias[col], bhi = bias[col + 1];
            *(float2*)&C[(size_t)r0       * Nc + col] =
                make_float2(acc[mt][nt][0] + blo, acc[mt][nt][1] + bhi);
            *(float2*)&C[(size_t)(r0 + 8) * Nc + col] =
                make_float2(acc[mt][nt][2] + blo, acc[mt][nt][3] + bhi);
        }
    }
}

// ==================== fused attention: scores+bias+mask+softmax+PV ===========
#define FA_KD   0
#define FA_VD   (24*385)
#define FA_QS   (2*24*385)
#define FA_MK   (2*24*385 + 384*25)
#define FA_SMEM ((2*24*385 + 384*25 + 384) * 4)

__global__ void __launch_bounds__(256, 1)
fattn_k(const float* __restrict__ qkv, const float* __restrict__ bias,
        const int* __restrict__ nt,
        __nv_bfloat16* __restrict__ oh, __nv_bfloat16* __restrict__ ol) {
    extern __shared__ float fs[];
    float* kd = fs + FA_KD;
    float* vd = fs + FA_VD;
    float* qs = fs + FA_QS;
    float* mk = fs + FA_MK;
    int bh = blockIdx.x;
    int b = bh >> 5, h = bh & 31;
    int tid = threadIdx.x, w = tid >> 5, lane = tid & 31;
    const float scaling = 0.20412414523193154f;   // 24^-0.5

    for (int i = tid; i < 384*24; i += 256) {
        int m = i / 24, d = i % 24;
        size_t base = ((size_t)m*B_ + b)*QKV + h*D_ + d;
        qs[m*25 + d]  = qkv[base] * scaling;
        kd[d*385 + m] = qkv[base + E_];
        vd[d*385 + m] = qkv[base + 2*E_];
    }
    for (int i = tid; i < 384; i += 256)
        mk[i] = (nt[b*Nn + i] == 0) ? -1e30f : 0.f;
    __syncthreads();

    for (int g = 0; g < 12; g++) {
        int r0 = g*32 + w*4;
        float sv[4][12];
#pragma unroll
        for (int r = 0; r < 4; r++)
#pragma unroll
            for (int j = 0; j < 12; j++) sv[r][j] = 0.f;

#pragma unroll
        for (int db = 0; db < 4; db++) {
            float qreg[4][6];
#pragma unroll
            for (int r = 0; r < 4; r++)
#pragma unroll
                for (int dd = 0; dd < 6; dd++)
                    qreg[r][dd] = qs[(r0 + r)*25 + db*6 + dd];
#pragma unroll
            for (int j = 0; j < 12; j++) {
                int m = lane + 32*j;
#pragma unroll
                for (int dd = 0; dd < 6; dd++) {
                    float kv = kd[(db*6 + dd)*385 + m];
#pragma unroll
                    for (int r = 0; r < 4; r++)
                        sv[r][j] = fmaf(qreg[r][dd], kv, sv[r][j]);
                }
            }
        }

#pragma unroll
        for (int r = 0; r < 4; r++) {
            int n = r0 + r;
            const float* brow = bias + ((size_t)bh*Nn + n)*Nn;
            float mx = -3.4e38f;
#pragma unroll
            for (int j = 0; j < 12; j++) {
                int m = lane + 32*j;
                float val = sv[r][j] + brow[m] + mk[m];
                sv[r][j] = val; mx = fmaxf(mx, val);
            }
            for (int o = 16; o; o >>= 1) mx = fmaxf(mx, __shfl_xor_sync(0xffffffffu, mx, o));
            float sum = 0.f;
#pragma unroll
            for (int j = 0; j < 12; j++) {
                float e = __expf(sv[r][j] - mx); sv[r][j] = e; sum += e;
            }
            for (int o = 16; o; o >>= 1) sum += __shfl_xor_sync(0xffffffffu, sum, o);
            float inv = 1.f / sum;
#pragma unroll
            for (int j = 0; j < 12; j++) sv[r][j] *= inv;
        }

        float acc[4][24];
#pragma unroll
        for (int r = 0; r < 4; r++)
#pragma unroll
            for (int d = 0; d < 24; d++) acc[r][d] = 0.f;
#pragma unroll
        for (int j = 0; j < 12; j++) {
            int m = lane + 32*j;
#pragma unroll
            for (int d = 0; d < 24; d++) {
                float v = vd[d*385 + m];
#pragma unroll
                for (int r = 0; r < 4; r++)
                    acc[r][d] = fmaf(sv[r][j], v, acc[r][d]);
            }
        }

#pragma unroll
        for (int r = 0; r < 4; r++) {
            int n = r0 + r;
            float myv = 0.f;
#pragma unroll
            for (int d = 0; d < 24; d++) {
                float t = acc[r][d];
                for (int o = 16; o; o >>= 1) t += __shfl_xor_sync(0xffffffffu, t, o);
                if (lane == d) myv = t;
            }
            if (lane < 24) {
                size_t idx = ((size_t)n*B_ + b)*E_ + h*D_ + lane;
                __nv_bfloat16 hv, lv; split_bf(myv, hv, lv);
                oh[idx] = hv; ol[idx] = lv;
            }
        }
    }
}

// ==================== residual add + LayerNorm (+ bf16 hi/lo out) ============
__global__ void __launch_bounds__(256)
ln_k(const float* __restrict__ x, const float* __restrict__ a,
     const float* __restrict__ s, const float* __restrict__ bb,
     float* __restrict__ out,
     __nv_bfloat16* __restrict__ oh, __nv_bfloat16* __restrict__ ol) {
    __shared__ float r1[8], r2[8];
    int t = blockIdx.x, tid = threadIdx.x;
    const float* xp = x + (size_t)t * E_;
    const float* ap = a + (size_t)t * E_;
    float v[3]; float sum = 0.f;
#pragma unroll
    for (int i = 0; i < 3; i++) { int e = tid + (i << 8); v[i] = xp[e] + ap[e]; sum += v[i]; }
    for (int o = 16; o; o >>= 1) sum += __shfl_xor_sync(0xffffffffu, sum, o);
    if ((tid & 31) == 0) r1[tid >> 5] = sum;
    __syncthreads();
    sum = 0.f;
#pragma unroll
    for (int w = 0; w < 8; w++) sum += r1[w];
    float mu = sum * (1.f / 768.f);
    float var = 0.f;
#pragma unroll
    for (int i = 0; i < 3; i++) { float d = v[i] - mu; var += d * d; }
    for (int o = 16; o; o >>= 1) var += __shfl_xor_sync(0xffffffffu, var, o);
    if ((tid & 31) == 0) r2[tid >> 5] = var;
    __syncthreads();
    var = 0.f;
#pragma unroll
    for (int w = 0; w < 8; w++) var += r2[w];
    float rstd = rsqrtf(var * (1.f / 768.f) + 1e-5f);
#pragma unroll
    for (int i = 0; i < 3; i++) {
        int e = tid + (i << 8);
        float o = (v[i] - mu) * rstd * s[e] + bb[e];
        out[(size_t)t * E_ + e] = o;
        __nv_bfloat16 hh, ll; split_bf(o, hh, ll);
        oh[(size_t)t * E_ + e] = hh; ol[(size_t)t * E_ + e] = ll;
    }
}

// ==================== orchestration ====================
extern "C" void kernel_launch(void* const* d_in, const int* in_sizes, int n_in,
                              void* d_out, int out_size) {
    const int*   nt    = (const int*)  d_in[0];
    const float* nif   = (const float*)d_in[1];
    const int*   ind   = (const int*)  d_in[2];
    const int*   outd  = (const int*)  d_in[3];
    const float* ab    = (const float*)d_in[4];
    const int*   sp    = (const int*)  d_in[5];
    const float* nemb  = (const float*)d_in[6];
    const float* iemb  = (const float*)d_in[7];
    const float* oemb  = (const float*)d_in[8];
    const float* se    = (const float*)d_in[9];
    const float* ser   = (const float*)d_in[10];
    const float* Wq    = (const float*)d_in[11];
    const float* bq    = (const float*)d_in[12];
    const float* Wk    = (const float*)d_in[13];
    const float* bk    = (const float*)d_in[14];
    const float* Wv    = (const float*)d_in[15];
    const float* bv    = (const float*)d_in[16];
    const float* Wo    = (const float*)d_in[17];
    const float* bo    = (const float*)d_in[18];
    const float* W1    = (const float*)d_in[19];
    const float* b1    = (const float*)d_in[20];
    const float* W2    = (const float*)d_in[21];
    const float* b2    = (const float*)d_in[22];
    const float* ln1s  = (const float*)d_in[23];
    const float* ln1b  = (const float*)d_in[24];
    const float* ln2s  = (const float*)d_in[25];
    const float* ln2b  = (const float*)d_in[26];
    float* out = (float*)d_out;

    float *x, *tmp, *qkv, *bias, *bqkv;
    __nv_bfloat16 *xh, *xl, *ch, *cl, *hh, *hl;
    __nv_bfloat16 *wqkvh, *wqkvl, *woh, *wol, *w1h, *w1l, *w2h, *w2l;
    cudaGetSymbolAddress((void**)&x,    g_x);
    cudaGetSymbolAddress((void**)&tmp,  g_tmp);
    cudaGetSymbolAddress((void**)&qkv,  g_qkv);
    cudaGetSymbolAddress((void**)&bias, g_bias);
    cudaGetSymbolAddress((void**)&bqkv, g_bqkv);
    cudaGetSymbolAddress((void**)&xh,   g_xh);
    cudaGetSymbolAddress((void**)&xl,   g_xl);
    cudaGetSymbolAddress((void**)&ch,   g_ch);
    cudaGetSymbolAddress((void**)&cl,   g_cl);
    cudaGetSymbolAddress((void**)&hh,   g_hh);
    cudaGetSymbolAddress((void**)&hl,   g_hl);
    cudaGetSymbolAddress((void**)&wqkvh, g_wqkvh);
    cudaGetSymbolAddress((void**)&wqkvl, g_wqkvl);
    cudaGetSymbolAddress((void**)&woh,   g_woh);
    cudaGetSymbolAddress((void**)&wol,   g_wol);
    cudaGetSymbolAddress((void**)&w1h,   g_w1h);
    cudaGetSymbolAddress((void**)&w1l,   g_w1l);
    cudaGetSymbolAddress((void**)&w2h,   g_w2h);
    cudaGetSymbolAddress((void**)&w2l,   g_w2l);

    cudaFuncSetAttribute(mma_gemm<0>, cudaFuncAttributeMaxDynamicSharedMemorySize, GSMT);
    cudaFuncSetAttribute(mma_gemm<1>, cudaFuncAttributeMaxDynamicSharedMemorySize, GSMT);
    cudaFuncSetAttribute(mma_gemm64, cudaFuncAttributeMaxDynamicSharedMemorySize, GSMT64);
    cudaFuncSetAttribute(fattn_k, cudaFuncAttributeMaxDynamicSharedMemorySize, FA_SMEM);

    // ---- prepass: 3 launches, so our idx 3 == first QKV GEMM (profiled slot) ----
    trall_k<<<TRALL_BLOCKS, 256>>>(Wq, Wk, Wv, Wo, W1, W2,
                                   wqkvh, wqkvl, woh, wol,
                                   w1h, w1l, w2h, w2l);                     // idx 0
    embed_packb_k<<<4608 + 108, 256>>>(nt, nif, ind, outd, nemb, iemb, oemb,
                                       x, xh, xl, bq, bk, bv, bqkv);        // idx 1
    bias_k<<<dim3(B_, Nn/32, Nn/32), 256>>>(sp, ab, se, ser, bias);         // idx 2

    dim3 gQKV(QKV/64, T_/128);     // (36, 12)
    dim3 gE64(E_/64, T_/64);       // (12, 24) = 288 blocks
    dim3 gF1(F_/64, T_/128);       // (48, 12)

    for (int l = 0; l < L_; l++) {
        mma_gemm<0><<<gQKV, 256, GSMT>>>(xh, xl,
            wqkvh + (size_t)l*QKV*E_, wqkvl + (size_t)l*QKV*E_,
            bqkv + l*QKV, qkv, hh, hl, T_, E_, QKV, 1.f);                   // idx 3 (l=0)

        fattn_k<<<B_*H_, 256, FA_SMEM>>>(qkv, bias, nt, ch, cl);

        mma_gemm64<<<gE64, 128, GSMT64>>>(ch, cl,
            woh + (size_t)l*E_*E_, wol + (size_t)l*E_*E_,
            bo + l*E_, tmp, T_, E_, E_);
        ln_k<<<T_, 256>>>(x, tmp, ln1s + l*E_, ln1b + l*E_, x, xh, xl);

        mma_gemm<1><<<gF1, 256, GSMT>>>(xh, xl,
            w1h + (size_t)l*F_*E_, w1l + (size_t)l*F_*E_,
            b1 + l*F_, tmp, hh, hl, T_, E_, F_, 1.f);
        mma_gemm64<<<gE64, 128, GSMT64>>>(hh, hl,
            w2h + (size_t)l*E_*F_, w2l + (size_t)l*E_*F_,
            b2 + l*E_, tmp, T_, F_, E_);

        float* dst = (l == L_-1) ? out : x;
        ln_k<<<T_, 256>>>(x, tmp, ln2s + l*E_, ln2b + l*E_, dst, xh, xl);
    }
}